// round 10
// baseline (speedup 1.0000x reference)
#include <cuda_runtime.h>
#include <math_constants.h>

#define N_NODES 50000
#define N_EDGES 800000
#define DIM 64
#define NCHUNK 98          // 98*512 = 50176 >= 50000 ; co-resident for lookback scan
#define NQ (N_EDGES / 4)
#define NHALF (NQ / 2)

// ---- device scratch (no allocations allowed; static zero-init) ----
__device__ int   g_counts[N_NODES];      // invariant: zero at entry of every replay
__device__ int   g_offsets[N_NODES + 1];
__device__ int   g_cursor[N_NODES];
__device__ int   g_csum[NCHUNK];
__device__ volatile int g_cflag[NCHUNK]; // invariant: zero at entry (reset by k_scatter)
__device__ int   g_srcidx[N_EDGES];
__device__ float g_h0[N_NODES * DIM];
__device__ float g_h1[N_NODES * DIM];

// ---- packed f32x2 helpers (Blackwell FFMA2 path, PTX-only) ----
__device__ __forceinline__ unsigned long long pk2(float lo, float hi) {
    unsigned long long r;
    asm("mov.b64 %0, {%1, %2};" : "=l"(r) : "f"(lo), "f"(hi));
    return r;
}
__device__ __forceinline__ void fma2(unsigned long long& d,
                                     unsigned long long a,
                                     unsigned long long b) {
    asm("fma.rn.f32x2 %0, %1, %2, %0;" : "+l"(d) : "l"(a), "l"(b));
}
__device__ __forceinline__ void upk2(float& lo, float& hi, unsigned long long v) {
    asm("mov.b64 {%0, %1}, %2;" : "=f"(lo), "=f"(hi) : "l"(v));
}

// ---------------- CSR build ----------------

__global__ void k_count(const int* __restrict__ dst) {
    int i = blockIdx.x * blockDim.x + threadIdx.x;
    if (i < NHALF) {
        int4 a = __ldg((const int4*)dst + i);
        int4 b = __ldg((const int4*)dst + i + NHALF);
        atomicAdd(&g_counts[a.x], 1);
        atomicAdd(&g_counts[a.y], 1);
        atomicAdd(&g_counts[a.z], 1);
        atomicAdd(&g_counts[a.w], 1);
        atomicAdd(&g_counts[b.x], 1);
        atomicAdd(&g_counts[b.y], 1);
        atomicAdd(&g_counts[b.z], 1);
        atomicAdd(&g_counts[b.w], 1);
    }
}

// single-kernel scan via decoupled lookback (all 98 blocks co-resident)
__global__ void __launch_bounds__(512) k_scan() {
    __shared__ int warp_sums[16];
    __shared__ int prefix_s;
    const int t = threadIdx.x, lane = t & 31, wid = t >> 5;
    const int c = blockIdx.x;
    const int i = c * 512 + t;

    int v = (i < N_NODES) ? g_counts[i] : 0;
    int s = v;
    #pragma unroll
    for (int d = 1; d < 32; d <<= 1) {
        int y = __shfl_up_sync(0xffffffffu, s, d);
        if (lane >= d) s += y;
    }
    if (lane == 31) warp_sums[wid] = s;
    __syncthreads();
    if (wid == 0 && lane < 16) {
        int ws = warp_sums[lane];
        #pragma unroll
        for (int d = 1; d < 16; d <<= 1) {
            int y = __shfl_up_sync(0xffffu, ws, d);
            if (lane >= d) ws += y;
        }
        warp_sums[lane] = ws;
    }
    __syncthreads();
    int excl = s - v + (wid > 0 ? warp_sums[wid - 1] : 0);

    if (t == 511) {
        g_csum[c] = excl + v;
        __threadfence();
        g_cflag[c] = 1;
    }
    if (t < 32) {
        int acc = 0;
        for (int j = lane; j < c; j += 32) {
            while (g_cflag[j] == 0) { }
            acc += *(volatile int*)&g_csum[j];
        }
        #pragma unroll
        for (int d = 16; d > 0; d >>= 1) acc += __shfl_down_sync(0xffffffffu, acc, d);
        if (lane == 0) prefix_s = acc;
    }
    __syncthreads();
    int prefix = prefix_s;

    if (i < N_NODES) {
        int o = excl + prefix;
        g_offsets[i] = o;
        g_cursor[i]  = o;
        g_counts[i]  = 0;
    }
    if (c == NCHUNK - 1 && t == 511)
        g_offsets[N_NODES] = prefix + excl + v;
}

__global__ void k_scatter(const int* __restrict__ src, const int* __restrict__ dst) {
    int i = blockIdx.x * blockDim.x + threadIdx.x;
    if (i < NCHUNK) g_cflag[i] = 0;
    if (i < NHALF) {
        int4 sa = __ldg((const int4*)src + i);
        int4 da = __ldg((const int4*)dst + i);
        int4 sb = __ldg((const int4*)src + i + NHALF);
        int4 db = __ldg((const int4*)dst + i + NHALF);
        g_srcidx[atomicAdd(&g_cursor[da.x], 1)] = sa.x;
        g_srcidx[atomicAdd(&g_cursor[da.y], 1)] = sa.y;
        g_srcidx[atomicAdd(&g_cursor[da.z], 1)] = sa.z;
        g_srcidx[atomicAdd(&g_cursor[da.w], 1)] = sa.w;
        g_srcidx[atomicAdd(&g_cursor[db.x], 1)] = sb.x;
        g_srcidx[atomicAdd(&g_cursor[db.y], 1)] = sb.y;
        g_srcidx[atomicAdd(&g_cursor[db.z], 1)] = sb.z;
        g_srcidx[atomicAdd(&g_cursor[db.w], 1)] = sb.w;
    }
}

// ---------------- fused layer: agg (segment-max) + GEMM + bias + leaky-relu ----
// 512 threads, tile = 64 nodes.
// Agg: warp per node (4 nodes/warp), float2 gathers, batch-8 with index prefetch.
// GEMM: thread = (node t>>3, 8-col group t&7). W read as 2x LDS.128 per k
//       (1 phase each within a warp), x as 1x LDS.128 per 4 k (broadcast).
//       Packed f32x2 FMA accumulators.
__global__ void __launch_bounds__(512, 3) k_layer(
        const float* __restrict__ h,
        const float* __restrict__ W,
        const float* __restrict__ bias,
        const float* __restrict__ eps, int layer,
        float* __restrict__ out, int activate) {
    __shared__ float Ws[64 * 64];     // [k][j]
    __shared__ float Xs[64 * 68];     // [node][k], padded stride 68 (272B = 17*16B)

    int t = threadIdx.x;              // 0..511
    int base = blockIdx.x * 64;

    // load W via float4 (1024 float4 over 512 threads)
    const float4* W4 = (const float4*)W;
    float4* Ws4 = (float4*)Ws;
    Ws4[t]       = W4[t];
    Ws4[t + 512] = W4[t + 512];

    float ep = 1.0f + __ldg(eps + layer);
    int warp = t >> 5, lane = t & 31;

    // ---- phase 1: aggregation with pipelined index prefetch ----
    #pragma unroll
    for (int q = 0; q < 4; q++) {
        int nl = warp * 4 + q;
        int n = base + nl;
        if (n < N_NODES) {
            int beg = g_offsets[n];
            int end = g_offsets[n + 1];
            float m0 = -CUDART_INF_F, m1 = -CUDART_INF_F;
            int i = beg;
            int cur[8];
            bool have = (i + 8 <= end);
            if (have) {
                #pragma unroll
                for (int u = 0; u < 8; u++) cur[u] = __ldg(&g_srcidx[i + u]);
            }
            while (have) {
                int ni = i + 8;
                bool nhave = (ni + 8 <= end);
                int nxt[8];
                if (nhave) {
                    #pragma unroll
                    for (int u = 0; u < 8; u++) nxt[u] = __ldg(&g_srcidx[ni + u]);
                }
                float2 a[8];
                #pragma unroll
                for (int u = 0; u < 8; u++)
                    a[u] = __ldg((const float2*)(h + (size_t)cur[u] * DIM) + lane);
                #pragma unroll
                for (int u = 0; u < 8; u++) {
                    m0 = fmaxf(m0, a[u].x);
                    m1 = fmaxf(m1, a[u].y);
                }
                i = ni;
                #pragma unroll
                for (int u = 0; u < 8; u++) cur[u] = nxt[u];
                have = nhave;
            }
            for (; i < end; ++i) {
                int s = __ldg(&g_srcidx[i]);
                float2 a = __ldg((const float2*)(h + (size_t)s * DIM) + lane);
                m0 = fmaxf(m0, a.x);
                m1 = fmaxf(m1, a.y);
            }
            if (beg == end) { m0 = 0.0f; m1 = 0.0f; }   // DGL zero-fill
            float2 hs = __ldg((const float2*)(h + (size_t)n * DIM) + lane);
            float2 xv;
            xv.x = fmaf(ep, hs.x, m0);
            xv.y = fmaf(ep, hs.y, m1);
            *(float2*)&Xs[nl * 68 + lane * 2] = xv;
        }
    }
    __syncthreads();

    // ---- phase 2: GEMM out[64x64] = Xs @ Ws + b (8 cols x 1 node / thread) ----
    int jg = t & 7;                   // col group: cols jg*8 .. jg*8+7
    int nl = t >> 3;                  // local node 0..63

    // bias for 8 cols as 4 packed pairs
    const unsigned long long* bp = (const unsigned long long*)(bias + jg * 8);
    unsigned long long acc0 = bp[0], acc1 = bp[1], acc2 = bp[2], acc3 = bp[3];

    #pragma unroll
    for (int kc = 0; kc < 64; kc += 4) {
        float4 xv = *(const float4*)&Xs[nl * 68 + kc];
        #pragma unroll
        for (int u = 0; u < 4; u++) {
            const unsigned long long* wp =
                (const unsigned long long*)&Ws[(kc + u) * 64 + jg * 8];
            unsigned long long w0 = wp[0], w1 = wp[1], w2 = wp[2], w3 = wp[3];
            float xk = (u == 0) ? xv.x : (u == 1) ? xv.y : (u == 2) ? xv.z : xv.w;
            unsigned long long xp = pk2(xk, xk);
            fma2(acc0, xp, w0);
            fma2(acc1, xp, w1);
            fma2(acc2, xp, w2);
            fma2(acc3, xp, w3);
        }
    }

    int n = base + nl;
    if (n < N_NODES) {
        float r[8];
        upk2(r[0], r[1], acc0);
        upk2(r[2], r[3], acc1);
        upk2(r[4], r[5], acc2);
        upk2(r[6], r[7], acc3);
        if (activate) {
            #pragma unroll
            for (int u = 0; u < 8; u++) r[u] = r[u] >= 0.f ? r[u] : 0.01f * r[u];
        }
        float4 v0 = make_float4(r[0], r[1], r[2], r[3]);
        float4 v1 = make_float4(r[4], r[5], r[6], r[7]);
        *(float4*)&out[(size_t)n * DIM + jg * 8]     = v0;
        *(float4*)&out[(size_t)n * DIM + jg * 8 + 4] = v1;
    }
}

// ---------------- launch ----------------
extern "C" void kernel_launch(void* const* d_in, const int* in_sizes, int n_in,
                              void* d_out, int out_size) {
    const float* n_feat = (const float*)d_in[0];
    const float* W0 = (const float*)d_in[1];
    const float* b0 = (const float*)d_in[2];
    const float* W1 = (const float*)d_in[3];
    const float* b1 = (const float*)d_in[4];
    const float* W2 = (const float*)d_in[5];
    const float* b2 = (const float*)d_in[6];
    const float* eps = (const float*)d_in[7];
    const int*   src = (const int*)d_in[8];
    const int*   dst = (const int*)d_in[9];
    float* out = (float*)d_out;

    float *h0_ptr, *h1_ptr;
    cudaGetSymbolAddress((void**)&h0_ptr, g_h0);
    cudaGetSymbolAddress((void**)&h1_ptr, g_h1);

    // CSR build (3 launches)
    k_count<<<(NHALF + 255) / 256, 256>>>(dst);
    k_scan<<<NCHUNK, 512>>>();
    k_scatter<<<(NHALF + 255) / 256, 256>>>(src, dst);

    const int layer_blocks = (N_NODES + 63) / 64;   // 782

    k_layer<<<layer_blocks, 512>>>(n_feat, W0, b0, eps, 0, h0_ptr, 1);
    k_layer<<<layer_blocks, 512>>>(h0_ptr, W1, b1, eps, 1, h1_ptr, 1);
    k_layer<<<layer_blocks, 512>>>(h1_ptr, W2, b2, eps, 2, out, 0);
}

// round 11
// speedup vs baseline: 2.8840x; 2.8840x over previous
#include <cuda_runtime.h>
#include <cuda_fp16.h>
#include <math_constants.h>

#define N_NODES 50000
#define N_EDGES 800000
#define DIM 64
#define NCHUNK 98          // 98*512 = 50176 >= 50000 ; co-resident for lookback scan
#define NQ (N_EDGES / 4)
#define NHALF (NQ / 2)

// ---- device scratch (no allocations allowed; static zero-init) ----
__device__ int   g_counts[N_NODES];      // invariant: zero at entry of every replay
__device__ int   g_offsets[N_NODES + 1];
__device__ int   g_cursor[N_NODES];
__device__ int   g_csum[NCHUNK];
__device__ volatile int g_cflag[NCHUNK]; // invariant: zero at entry (reset by k_scatter)
__device__ int   g_srcidx[N_EDGES];
__device__ float g_h0[N_NODES * DIM];
__device__ float g_h1[N_NODES * DIM];
__device__ __align__(16) __half g_hha[N_NODES * DIM];  // fp16 shadow (ping)
__device__ __align__(16) __half g_hhb[N_NODES * DIM];  // fp16 shadow (pong)

// ---- packed f32x2 helpers (Blackwell FFMA2 path, PTX-only) ----
__device__ __forceinline__ unsigned long long pk2(float lo, float hi) {
    unsigned long long r;
    asm("mov.b64 %0, {%1, %2};" : "=l"(r) : "f"(lo), "f"(hi));
    return r;
}
__device__ __forceinline__ void fma2(unsigned long long& d,
                                     unsigned long long a,
                                     unsigned long long b) {
    asm("fma.rn.f32x2 %0, %1, %2, %0;" : "+l"(d) : "l"(a), "l"(b));
}
__device__ __forceinline__ void upk2(float& lo, float& hi, unsigned long long v) {
    asm("mov.b64 {%0, %1}, %2;" : "=f"(lo), "=f"(hi) : "l"(v));
}

// ---------------- CSR build ----------------

__global__ void k_count(const int* __restrict__ dst) {
    int i = blockIdx.x * blockDim.x + threadIdx.x;
    if (i < NHALF) {
        int4 a = __ldg((const int4*)dst + i);
        int4 b = __ldg((const int4*)dst + i + NHALF);
        atomicAdd(&g_counts[a.x], 1);
        atomicAdd(&g_counts[a.y], 1);
        atomicAdd(&g_counts[a.z], 1);
        atomicAdd(&g_counts[a.w], 1);
        atomicAdd(&g_counts[b.x], 1);
        atomicAdd(&g_counts[b.y], 1);
        atomicAdd(&g_counts[b.z], 1);
        atomicAdd(&g_counts[b.w], 1);
    }
}

// n_feat -> fp16 shadow (8 floats per thread)
__global__ void k_conv(const float* __restrict__ f) {
    int i = blockIdx.x * blockDim.x + threadIdx.x;
    if (i < N_NODES * DIM / 8) {
        float4 v0 = __ldg((const float4*)f + i * 2);
        float4 v1 = __ldg((const float4*)f + i * 2 + 1);
        __half2 hs[4];
        hs[0] = __floats2half2_rn(v0.x, v0.y);
        hs[1] = __floats2half2_rn(v0.z, v0.w);
        hs[2] = __floats2half2_rn(v1.x, v1.y);
        hs[3] = __floats2half2_rn(v1.z, v1.w);
        *(uint4*)((__half2*)g_hha + i * 4) = *(uint4*)hs;
    }
}

// single-kernel scan via decoupled lookback (all 98 blocks co-resident)
__global__ void __launch_bounds__(512) k_scan() {
    __shared__ int warp_sums[16];
    __shared__ int prefix_s;
    const int t = threadIdx.x, lane = t & 31, wid = t >> 5;
    const int c = blockIdx.x;
    const int i = c * 512 + t;

    int v = (i < N_NODES) ? g_counts[i] : 0;
    int s = v;
    #pragma unroll
    for (int d = 1; d < 32; d <<= 1) {
        int y = __shfl_up_sync(0xffffffffu, s, d);
        if (lane >= d) s += y;
    }
    if (lane == 31) warp_sums[wid] = s;
    __syncthreads();
    if (wid == 0 && lane < 16) {
        int ws = warp_sums[lane];
        #pragma unroll
        for (int d = 1; d < 16; d <<= 1) {
            int y = __shfl_up_sync(0xffffu, ws, d);
            if (lane >= d) ws += y;
        }
        warp_sums[lane] = ws;
    }
    __syncthreads();
    int excl = s - v + (wid > 0 ? warp_sums[wid - 1] : 0);

    if (t == 511) {
        g_csum[c] = excl + v;
        __threadfence();
        g_cflag[c] = 1;
    }
    if (t < 32) {
        int acc = 0;
        for (int j = lane; j < c; j += 32) {
            while (g_cflag[j] == 0) { }
            acc += *(volatile int*)&g_csum[j];
        }
        #pragma unroll
        for (int d = 16; d > 0; d >>= 1) acc += __shfl_down_sync(0xffffffffu, acc, d);
        if (lane == 0) prefix_s = acc;
    }
    __syncthreads();
    int prefix = prefix_s;

    if (i < N_NODES) {
        int o = excl + prefix;
        g_offsets[i] = o;
        g_cursor[i]  = o;
        g_counts[i]  = 0;
    }
    if (c == NCHUNK - 1 && t == 511)
        g_offsets[N_NODES] = prefix + excl + v;
}

__global__ void k_scatter(const int* __restrict__ src, const int* __restrict__ dst) {
    int i = blockIdx.x * blockDim.x + threadIdx.x;
    if (i < NCHUNK) g_cflag[i] = 0;
    if (i < NHALF) {
        int4 sa = __ldg((const int4*)src + i);
        int4 da = __ldg((const int4*)dst + i);
        int4 sb = __ldg((const int4*)src + i + NHALF);
        int4 db = __ldg((const int4*)dst + i + NHALF);
        g_srcidx[atomicAdd(&g_cursor[da.x], 1)] = sa.x;
        g_srcidx[atomicAdd(&g_cursor[da.y], 1)] = sa.y;
        g_srcidx[atomicAdd(&g_cursor[da.z], 1)] = sa.z;
        g_srcidx[atomicAdd(&g_cursor[da.w], 1)] = sa.w;
        g_srcidx[atomicAdd(&g_cursor[db.x], 1)] = sb.x;
        g_srcidx[atomicAdd(&g_cursor[db.y], 1)] = sb.y;
        g_srcidx[atomicAdd(&g_cursor[db.z], 1)] = sb.z;
        g_srcidx[atomicAdd(&g_cursor[db.w], 1)] = sb.w;
    }
}

// ---------------- fused layer: agg (fp16 segment-max) + fp32 GEMM ----------------
// 512 threads, tile = 64 nodes.
// Agg: warp per node, HALF2 gathers from fp16 shadow (128B/edge), index prefetch.
// GEMM: R8 structure — 2 nodes x 4 cols per thread, packed f32x2 FMA.
// Epilogue: fp32 out + fp16 shadow for next layer (when write_hh).
__global__ void __launch_bounds__(512, 3) k_layer(
        const float* __restrict__ h,          // fp32 h (self term)
        const __half* __restrict__ hh,        // fp16 shadow of h (gathers)
        const float* __restrict__ W,
        const float* __restrict__ bias,
        const float* __restrict__ eps, int layer,
        float* __restrict__ out,
        __half* __restrict__ hh_out,          // fp16 shadow of out (or unused)
        int activate, int write_hh) {
    __shared__ float Ws[64 * 64];     // [k][j]
    __shared__ float Xs[64 * 68];     // padded stride 68

    int t = threadIdx.x;              // 0..511
    int base = blockIdx.x * 64;

    // load W via float4 (1024 float4 over 512 threads)
    const float4* W4 = (const float4*)W;
    float4* Ws4 = (float4*)Ws;
    Ws4[t]       = W4[t];
    Ws4[t + 512] = W4[t + 512];

    float ep = 1.0f + __ldg(eps + layer);
    int warp = t >> 5, lane = t & 31;

    // ---- phase 1: fp16 aggregation with pipelined index prefetch ----
    #pragma unroll
    for (int q = 0; q < 4; q++) {
        int nl = warp * 4 + q;
        int n = base + nl;
        if (n < N_NODES) {
            int beg = g_offsets[n];
            int end = g_offsets[n + 1];
            __half2 m = __float2half2_rn(-CUDART_INF_F);
            int i = beg;
            int cur[8];
            bool have = (i + 8 <= end);
            if (have) {
                #pragma unroll
                for (int u = 0; u < 8; u++) cur[u] = __ldg(&g_srcidx[i + u]);
            }
            while (have) {
                int ni = i + 8;
                bool nhave = (ni + 8 <= end);
                int nxt[8];
                if (nhave) {
                    #pragma unroll
                    for (int u = 0; u < 8; u++) nxt[u] = __ldg(&g_srcidx[ni + u]);
                }
                __half2 a[8];
                #pragma unroll
                for (int u = 0; u < 8; u++)
                    a[u] = __ldg((const __half2*)(hh + (size_t)cur[u] * DIM) + lane);
                #pragma unroll
                for (int u = 0; u < 8; u++) m = __hmax2(m, a[u]);
                i = ni;
                #pragma unroll
                for (int u = 0; u < 8; u++) cur[u] = nxt[u];
                have = nhave;
            }
            for (; i < end; ++i) {
                int s = __ldg(&g_srcidx[i]);
                __half2 a = __ldg((const __half2*)(hh + (size_t)s * DIM) + lane);
                m = __hmax2(m, a);
            }
            float2 mf = __half22float2(m);
            if (beg == end) { mf.x = 0.0f; mf.y = 0.0f; }   // DGL zero-fill
            float2 hs = __ldg((const float2*)(h + (size_t)n * DIM) + lane);
            float2 xv;
            xv.x = fmaf(ep, hs.x, mf.x);
            xv.y = fmaf(ep, hs.y, mf.y);
            *(float2*)&Xs[nl * 68 + lane * 2] = xv;
        }
    }
    __syncthreads();

    // ---- phase 2: GEMM out[64x64] = Xs @ Ws + b, packed f32x2 FMA ----
    int jg = t & 15;                  // column group (4 cols)
    int ng = t >> 4;                  // node group (2 nodes), 0..31

    float4 bj = *(const float4*)(bias + jg * 4);
    unsigned long long a00 = pk2(bj.x, bj.y);   // node0 cols 0-1
    unsigned long long a01 = pk2(bj.z, bj.w);   // node0 cols 2-3
    unsigned long long a10 = a00;               // node1 cols 0-1
    unsigned long long a11 = a01;               // node1 cols 2-3

    const unsigned long long* Wp = (const unsigned long long*)Ws;  // pairs
    int wrow = jg * 2;

    #pragma unroll
    for (int k = 0; k < 64; k++) {
        unsigned long long w01 = Wp[k * 32 + wrow];
        unsigned long long w23 = Wp[k * 32 + wrow + 1];
        float x0 = Xs[(ng * 2 + 0) * 68 + k];
        float x1 = Xs[(ng * 2 + 1) * 68 + k];
        unsigned long long x00 = pk2(x0, x0);
        unsigned long long x11 = pk2(x1, x1);
        fma2(a00, x00, w01);
        fma2(a01, x00, w23);
        fma2(a10, x11, w01);
        fma2(a11, x11, w23);
    }

    float r[2][4];
    upk2(r[0][0], r[0][1], a00);
    upk2(r[0][2], r[0][3], a01);
    upk2(r[1][0], r[1][1], a10);
    upk2(r[1][2], r[1][3], a11);

    #pragma unroll
    for (int i = 0; i < 2; i++) {
        int n = base + ng * 2 + i;
        if (n < N_NODES) {
            float4 v;
            v.x = r[i][0]; v.y = r[i][1]; v.z = r[i][2]; v.w = r[i][3];
            if (activate) {
                v.x = v.x >= 0.f ? v.x : 0.01f * v.x;
                v.y = v.y >= 0.f ? v.y : 0.01f * v.y;
                v.z = v.z >= 0.f ? v.z : 0.01f * v.z;
                v.w = v.w >= 0.f ? v.w : 0.01f * v.w;
            }
            *(float4*)&out[(size_t)n * DIM + jg * 4] = v;
            if (write_hh) {
                __half2 hp[2];
                hp[0] = __floats2half2_rn(v.x, v.y);
                hp[1] = __floats2half2_rn(v.z, v.w);
                *(uint2*)(hh_out + (size_t)n * DIM + jg * 4) = *(uint2*)hp;
            }
        }
    }
}

// ---------------- launch ----------------
extern "C" void kernel_launch(void* const* d_in, const int* in_sizes, int n_in,
                              void* d_out, int out_size) {
    const float* n_feat = (const float*)d_in[0];
    const float* W0 = (const float*)d_in[1];
    const float* b0 = (const float*)d_in[2];
    const float* W1 = (const float*)d_in[3];
    const float* b1 = (const float*)d_in[4];
    const float* W2 = (const float*)d_in[5];
    const float* b2 = (const float*)d_in[6];
    const float* eps = (const float*)d_in[7];
    const int*   src = (const int*)d_in[8];
    const int*   dst = (const int*)d_in[9];
    float* out = (float*)d_out;

    float *h0_ptr, *h1_ptr;
    __half *hha_ptr, *hhb_ptr;
    cudaGetSymbolAddress((void**)&h0_ptr, g_h0);
    cudaGetSymbolAddress((void**)&h1_ptr, g_h1);
    cudaGetSymbolAddress((void**)&hha_ptr, g_hha);
    cudaGetSymbolAddress((void**)&hhb_ptr, g_hhb);

    // CSR build + fp16 conversion of n_feat
    k_count<<<(NHALF + 255) / 256, 256>>>(dst);
    k_conv<<<(N_NODES * DIM / 8 + 255) / 256, 256>>>(n_feat);
    k_scan<<<NCHUNK, 512>>>();
    k_scatter<<<(NHALF + 255) / 256, 256>>>(src, dst);

    const int layer_blocks = (N_NODES + 63) / 64;   // 782

    // layer 0: gather hha (n_feat), write h0 + hhb
    k_layer<<<layer_blocks, 512>>>(n_feat, hha_ptr, W0, b0, eps, 0,
                                   h0_ptr, hhb_ptr, 1, 1);
    // layer 1: gather hhb, write h1 + hha
    k_layer<<<layer_blocks, 512>>>(h0_ptr, hhb_ptr, W1, b1, eps, 1,
                                   h1_ptr, hha_ptr, 1, 1);
    // layer 2: gather hha, write out only
    k_layer<<<layer_blocks, 512>>>(h1_ptr, hha_ptr, W2, b2, eps, 2,
                                   out, hhb_ptr, 0, 0);
}

// round 12
// speedup vs baseline: 2.9698x; 1.0297x over previous
#include <cuda_runtime.h>
#include <cuda_fp16.h>
#include <math_constants.h>

#define N_NODES 50000
#define N_EDGES 800000
#define DIM 64
#define NCHUNK 98          // 98*512 = 50176 >= 50000 ; co-resident for lookback scan
#define NCONV (N_NODES * DIM / 8)   // 400000 conv work-items (8 floats each)

// ---- device scratch (no allocations allowed; static zero-init) ----
__device__ int   g_counts[N_NODES];      // invariant: zero at entry of every replay
__device__ int   g_offsets[N_NODES + 1];
__device__ int   g_cursor[N_NODES];
__device__ int   g_csum[NCHUNK];
__device__ volatile int g_cflag[NCHUNK]; // invariant: zero at entry (reset by k_scatter)
__device__ int   g_srcidx[N_EDGES];
__device__ float g_h0[N_NODES * DIM];
__device__ float g_h1[N_NODES * DIM];
__device__ __align__(16) __half g_hha[N_NODES * DIM];  // fp16 shadow (ping)
__device__ __align__(16) __half g_hhb[N_NODES * DIM];  // fp16 shadow (pong)

// ---- packed f32x2 helpers (Blackwell FFMA2 path, PTX-only) ----
__device__ __forceinline__ unsigned long long pk2(float lo, float hi) {
    unsigned long long r;
    asm("mov.b64 %0, {%1, %2};" : "=l"(r) : "f"(lo), "f"(hi));
    return r;
}
__device__ __forceinline__ void fma2(unsigned long long& d,
                                     unsigned long long a,
                                     unsigned long long b) {
    asm("fma.rn.f32x2 %0, %1, %2, %0;" : "+l"(d) : "l"(a), "l"(b));
}
__device__ __forceinline__ void upk2(float& lo, float& hi, unsigned long long v) {
    asm("mov.b64 {%0, %1}, %2;" : "=f"(lo), "=f"(hi) : "l"(v));
}

// ---------------- CSR build ----------------

// fused: degree count (1 edge/thread, max TLP) + fp16 conversion of n_feat
__global__ void k_count_conv(const int* __restrict__ dst,
                             const float* __restrict__ f) {
    int i = blockIdx.x * blockDim.x + threadIdx.x;
    if (i < N_EDGES)
        atomicAdd(&g_counts[__ldg(dst + i)], 1);
    if (i < NCONV) {
        float4 v0 = __ldg((const float4*)f + i * 2);
        float4 v1 = __ldg((const float4*)f + i * 2 + 1);
        __half2 hs[4];
        hs[0] = __floats2half2_rn(v0.x, v0.y);
        hs[1] = __floats2half2_rn(v0.z, v0.w);
        hs[2] = __floats2half2_rn(v1.x, v1.y);
        hs[3] = __floats2half2_rn(v1.z, v1.w);
        *(uint4*)((__half2*)g_hha + i * 4) = *(uint4*)hs;
    }
}

// single-kernel scan via decoupled lookback (all 98 blocks co-resident)
__global__ void __launch_bounds__(512) k_scan() {
    __shared__ int warp_sums[16];
    __shared__ int prefix_s;
    const int t = threadIdx.x, lane = t & 31, wid = t >> 5;
    const int c = blockIdx.x;
    const int i = c * 512 + t;

    int v = (i < N_NODES) ? g_counts[i] : 0;
    int s = v;
    #pragma unroll
    for (int d = 1; d < 32; d <<= 1) {
        int y = __shfl_up_sync(0xffffffffu, s, d);
        if (lane >= d) s += y;
    }
    if (lane == 31) warp_sums[wid] = s;
    __syncthreads();
    if (wid == 0 && lane < 16) {
        int ws = warp_sums[lane];
        #pragma unroll
        for (int d = 1; d < 16; d <<= 1) {
            int y = __shfl_up_sync(0xffffu, ws, d);
            if (lane >= d) ws += y;
        }
        warp_sums[lane] = ws;
    }
    __syncthreads();
    int excl = s - v + (wid > 0 ? warp_sums[wid - 1] : 0);

    if (t == 511) {
        g_csum[c] = excl + v;
        __threadfence();
        g_cflag[c] = 1;
    }
    if (t < 32) {
        int acc = 0;
        for (int j = lane; j < c; j += 32) {
            while (g_cflag[j] == 0) { }
            acc += *(volatile int*)&g_csum[j];
        }
        #pragma unroll
        for (int d = 16; d > 0; d >>= 1) acc += __shfl_down_sync(0xffffffffu, acc, d);
        if (lane == 0) prefix_s = acc;
    }
    __syncthreads();
    int prefix = prefix_s;

    if (i < N_NODES) {
        int o = excl + prefix;
        g_offsets[i] = o;
        g_cursor[i]  = o;
        g_counts[i]  = 0;
    }
    if (c == NCHUNK - 1 && t == 511)
        g_offsets[N_NODES] = prefix + excl + v;
}

// 2 edges per thread (int2), 400K threads for latency hiding
__global__ void k_scatter(const int* __restrict__ src, const int* __restrict__ dst) {
    int i = blockIdx.x * blockDim.x + threadIdx.x;
    if (i < NCHUNK) g_cflag[i] = 0;              // flag reset (invariant)
    if (i < N_EDGES / 2) {
        int2 s2 = __ldg((const int2*)src + i);
        int2 d2 = __ldg((const int2*)dst + i);
        g_srcidx[atomicAdd(&g_cursor[d2.x], 1)] = s2.x;
        g_srcidx[atomicAdd(&g_cursor[d2.y], 1)] = s2.y;
    }
}

// ---------------- fused layer: agg (fp16 segment-max) + fp32 GEMM ----------------
__global__ void __launch_bounds__(512, 3) k_layer(
        const float* __restrict__ h,          // fp32 h (self term)
        const __half* __restrict__ hh,        // fp16 shadow of h (gathers)
        const float* __restrict__ W,
        const float* __restrict__ bias,
        const float* __restrict__ eps, int layer,
        float* __restrict__ out,
        __half* __restrict__ hh_out,          // fp16 shadow of out (or unused)
        int activate, int write_hh) {
    __shared__ float Ws[64 * 64];     // [k][j]
    __shared__ float Xs[64 * 68];     // padded stride 68

    int t = threadIdx.x;              // 0..511
    int base = blockIdx.x * 64;

    // load W via float4 (1024 float4 over 512 threads)
    const float4* W4 = (const float4*)W;
    float4* Ws4 = (float4*)Ws;
    Ws4[t]       = W4[t];
    Ws4[t + 512] = W4[t + 512];

    float ep = 1.0f + __ldg(eps + layer);
    int warp = t >> 5, lane = t & 31;

    // ---- phase 1: fp16 aggregation with pipelined index prefetch ----
    #pragma unroll
    for (int q = 0; q < 4; q++) {
        int nl = warp * 4 + q;
        int n = base + nl;
        if (n < N_NODES) {
            int beg = g_offsets[n];
            int end = g_offsets[n + 1];
            __half2 m = __float2half2_rn(-CUDART_INF_F);
            int i = beg;
            int cur[8];
            bool have = (i + 8 <= end);
            if (have) {
                #pragma unroll
                for (int u = 0; u < 8; u++) cur[u] = __ldg(&g_srcidx[i + u]);
            }
            while (have) {
                int ni = i + 8;
                bool nhave = (ni + 8 <= end);
                int nxt[8];
                if (nhave) {
                    #pragma unroll
                    for (int u = 0; u < 8; u++) nxt[u] = __ldg(&g_srcidx[ni + u]);
                }
                __half2 a[8];
                #pragma unroll
                for (int u = 0; u < 8; u++)
                    a[u] = __ldg((const __half2*)(hh + (size_t)cur[u] * DIM) + lane);
                #pragma unroll
                for (int u = 0; u < 8; u++) m = __hmax2(m, a[u]);
                i = ni;
                #pragma unroll
                for (int u = 0; u < 8; u++) cur[u] = nxt[u];
                have = nhave;
            }
            for (; i < end; ++i) {
                int s = __ldg(&g_srcidx[i]);
                __half2 a = __ldg((const __half2*)(hh + (size_t)s * DIM) + lane);
                m = __hmax2(m, a);
            }
            float2 mf = __half22float2(m);
            if (beg == end) { mf.x = 0.0f; mf.y = 0.0f; }   // DGL zero-fill
            float2 hs = __ldg((const float2*)(h + (size_t)n * DIM) + lane);
            float2 xv;
            xv.x = fmaf(ep, hs.x, mf.x);
            xv.y = fmaf(ep, hs.y, mf.y);
            *(float2*)&Xs[nl * 68 + lane * 2] = xv;
        }
    }
    __syncthreads();

    // ---- phase 2: GEMM out[64x64] = Xs @ Ws + b, packed f32x2 FMA ----
    int jg = t & 15;                  // column group (4 cols)
    int ng = t >> 4;                  // node group (2 nodes), 0..31

    float4 bj = *(const float4*)(bias + jg * 4);
    unsigned long long a00 = pk2(bj.x, bj.y);
    unsigned long long a01 = pk2(bj.z, bj.w);
    unsigned long long a10 = a00;
    unsigned long long a11 = a01;

    const unsigned long long* Wp = (const unsigned long long*)Ws;
    int wrow = jg * 2;

    #pragma unroll
    for (int k = 0; k < 64; k++) {
        unsigned long long w01 = Wp[k * 32 + wrow];
        unsigned long long w23 = Wp[k * 32 + wrow + 1];
        float x0 = Xs[(ng * 2 + 0) * 68 + k];
        float x1 = Xs[(ng * 2 + 1) * 68 + k];
        unsigned long long x00 = pk2(x0, x0);
        unsigned long long x11 = pk2(x1, x1);
        fma2(a00, x00, w01);
        fma2(a01, x00, w23);
        fma2(a10, x11, w01);
        fma2(a11, x11, w23);
    }

    float r[2][4];
    upk2(r[0][0], r[0][1], a00);
    upk2(r[0][2], r[0][3], a01);
    upk2(r[1][0], r[1][1], a10);
    upk2(r[1][2], r[1][3], a11);

    #pragma unroll
    for (int i = 0; i < 2; i++) {
        int n = base + ng * 2 + i;
        if (n < N_NODES) {
            float4 v;
            v.x = r[i][0]; v.y = r[i][1]; v.z = r[i][2]; v.w = r[i][3];
            if (activate) {
                v.x = v.x >= 0.f ? v.x : 0.01f * v.x;
                v.y = v.y >= 0.f ? v.y : 0.01f * v.y;
                v.z = v.z >= 0.f ? v.z : 0.01f * v.z;
                v.w = v.w >= 0.f ? v.w : 0.01f * v.w;
            }
            *(float4*)&out[(size_t)n * DIM + jg * 4] = v;
            if (write_hh) {
                __half2 hp[2];
                hp[0] = __floats2half2_rn(v.x, v.y);
                hp[1] = __floats2half2_rn(v.z, v.w);
                *(uint2*)(hh_out + (size_t)n * DIM + jg * 4) = *(uint2*)hp;
            }
        }
    }
}

// ---------------- launch ----------------
extern "C" void kernel_launch(void* const* d_in, const int* in_sizes, int n_in,
                              void* d_out, int out_size) {
    const float* n_feat = (const float*)d_in[0];
    const float* W0 = (const float*)d_in[1];
    const float* b0 = (const float*)d_in[2];
    const float* W1 = (const float*)d_in[3];
    const float* b1 = (const float*)d_in[4];
    const float* W2 = (const float*)d_in[5];
    const float* b2 = (const float*)d_in[6];
    const float* eps = (const float*)d_in[7];
    const int*   src = (const int*)d_in[8];
    const int*   dst = (const int*)d_in[9];
    float* out = (float*)d_out;

    float *h0_ptr, *h1_ptr;
    __half *hha_ptr, *hhb_ptr;
    cudaGetSymbolAddress((void**)&h0_ptr, g_h0);
    cudaGetSymbolAddress((void**)&h1_ptr, g_h1);
    cudaGetSymbolAddress((void**)&hha_ptr, g_hha);
    cudaGetSymbolAddress((void**)&hhb_ptr, g_hhb);

    // CSR build + fp16 conversion (3 launches)
    k_count_conv<<<(N_EDGES + 255) / 256, 256>>>(dst, n_feat);
    k_scan<<<NCHUNK, 512>>>();
    k_scatter<<<(N_EDGES / 2 + 255) / 256, 256>>>(src, dst);

    const int layer_blocks = (N_NODES + 63) / 64;   // 782

    k_layer<<<layer_blocks, 512>>>(n_feat, hha_ptr, W0, b0, eps, 0,
                                   h0_ptr, hhb_ptr, 1, 1);
    k_layer<<<layer_blocks, 512>>>(h0_ptr, hhb_ptr, W1, b1, eps, 1,
                                   h1_ptr, hha_ptr, 1, 1);
    k_layer<<<layer_blocks, 512>>>(h1_ptr, hha_ptr, W2, b2, eps, 2,
                                   out, hhb_ptr, 0, 0);
}